// round 14
// baseline (speedup 1.0000x reference)
#include <cuda_runtime.h>
#include <cuda_bf16.h>
#include <cstdint>

#define B_   16
#define N_   4096
#define C_   256
#define NH   8
#define HD   32
#define M_   (B_ * N_)

// ---------------- scratch ----------------
__device__ __align__(16) float g_Q[M_ * C_];
__device__ __align__(16) float g_K[M_ * C_];
__device__ __align__(16) float g_V[M_ * C_];
__device__ __align__(16) float g_O[M_ * C_];
__device__ __align__(16) float g_kmean[B_ * C_];
__device__ __align__(16) float g_kvmat[B_ * NH * HD * HD];
__device__ __align__(16) float g_rscale[C_];
__device__ __align__(16) __nv_bfloat16 g_xhi[M_ * C_];
__device__ __align__(16) __nv_bfloat16 g_xlo[M_ * C_];
__device__ __align__(16) __nv_bfloat16 g_ohi[M_ * C_];
__device__ __align__(16) __nv_bfloat16 g_olo[M_ * C_];
__device__ __align__(16) __nv_bfloat16 g_whi[4 * C_ * C_];   // [w][n][k]
__device__ __align__(16) __nv_bfloat16 g_wlo[4 * C_ * C_];

// ---------------- helpers ----------------
__device__ __forceinline__ uint32_t smem_u32(const void* p) {
    uint32_t a;
    asm("{ .reg .u64 t; cvta.to.shared.u64 t, %1; cvt.u32.u64 %0, t; }"
        : "=r"(a) : "l"(p));
    return a;
}
#define CPA(dst, src) \
    asm volatile("cp.async.cg.shared.global [%0], [%1], 16;" \
                 :: "r"(dst), "l"(__cvta_generic_to_global(src)) : "memory")
#define CPCOMMIT() asm volatile("cp.async.commit_group;" ::: "memory")
#define CPWAIT(n)  asm volatile("cp.async.wait_group %0;" :: "n"(n) : "memory")

#define LDSM4(d, addr) \
    asm volatile("ldmatrix.sync.aligned.m8n8.x4.shared.b16 {%0,%1,%2,%3}, [%4];" \
        : "=r"((d)[0]), "=r"((d)[1]), "=r"((d)[2]), "=r"((d)[3]) : "r"(addr))

#define MMA(c, a, b) \
    asm volatile("mma.sync.aligned.m16n8k16.row.col.f32.bf16.bf16.f32 " \
        "{%0,%1,%2,%3}, {%4,%5,%6,%7}, {%8,%9}, {%0,%1,%2,%3};" \
        : "+f"((c)[0]), "+f"((c)[1]), "+f"((c)[2]), "+f"((c)[3]) \
        : "r"((a)[0]), "r"((a)[1]), "r"((a)[2]), "r"((a)[3]), \
          "r"((b)[0]), "r"((b)[1]))

// ---------------- hi/lo conversion ----------------
union BF2U { __nv_bfloat162 b; uint32_t u; };
__device__ __forceinline__ void cvt4(float4 v, uint2& hi, uint2& lo) {
    __nv_bfloat16 h0 = __float2bfloat16_rn(v.x), h1 = __float2bfloat16_rn(v.y);
    __nv_bfloat16 h2 = __float2bfloat16_rn(v.z), h3 = __float2bfloat16_rn(v.w);
    __nv_bfloat16 l0 = __float2bfloat16_rn(v.x - __bfloat162float(h0));
    __nv_bfloat16 l1 = __float2bfloat16_rn(v.y - __bfloat162float(h1));
    __nv_bfloat16 l2 = __float2bfloat16_rn(v.z - __bfloat162float(h2));
    __nv_bfloat16 l3 = __float2bfloat16_rn(v.w - __bfloat162float(h3));
    BF2U a, b;
    a.b = __halves2bfloat162(h0, h1); b.b = __halves2bfloat162(h2, h3);
    hi = make_uint2(a.u, b.u);
    a.b = __halves2bfloat162(l0, l1); b.b = __halves2bfloat162(l2, l3);
    lo = make_uint2(a.u, b.u);
}

__global__ void cvt_hilo_kernel(const float* __restrict__ src,
                                __nv_bfloat16* __restrict__ hi,
                                __nv_bfloat16* __restrict__ lo, int n4)
{
    int i = blockIdx.x * 256 + threadIdx.x;
    if (i >= n4) return;
    float4 v = ((const float4*)src)[i];
    uint2 h, l;
    cvt4(v, h, l);
    ((uint2*)hi)[i] = h;
    ((uint2*)lo)[i] = l;
}

__global__ void prep_w_kernel(const float* __restrict__ Wq,
                              const float* __restrict__ Wkv,
                              const float* __restrict__ Wp)
{
    int k = blockIdx.x, w = blockIdx.y, n = threadIdx.x;
    float v;
    if      (w == 0) v = Wq[k * C_ + n];
    else if (w == 1) v = Wkv[k * 2 * C_ + n];
    else if (w == 2) v = Wkv[k * 2 * C_ + C_ + n];
    else             v = Wp[k * C_ + n];
    __nv_bfloat16 h = __float2bfloat16_rn(v);
    __nv_bfloat16 l = __float2bfloat16_rn(v - __bfloat162float(h));
    g_whi[(w * C_ + n) * C_ + k] = h;
    g_wlo[(w * C_ + n) * C_ + k] = l;
}

// precompute 1/softplus(scale_param); also zero kmean+kvmat accumulators
__global__ void prep_scale_zero_kernel(const float* __restrict__ scale_param)
{
    int t = blockIdx.x * 256 + threadIdx.x;
    if (blockIdx.x == 0) {
        float sp = scale_param[t];
        float s  = (sp > 20.f) ? sp : log1pf(expf(sp));
        g_rscale[t] = 1.f / s;
    }
    if (t < B_ * C_) g_kmean[t] = 0.f;
    if (t < B_ * NH * HD * HD) g_kvmat[t] = 0.f;
}

// ---------------- HMMA split-precision GEMM, 64x128 tile, 2 CTA/SM ------------
#define STAGE_SZ 49152
#define PL_AHI 0
#define PL_ALO 8192
#define PL_BHI 16384
#define PL_BLO 32768
#define SM_GTOT (2 * STAGE_SZ)

__global__ void __launch_bounds__(256, 2)
gemm_hmma(const __nv_bfloat16* __restrict__ Ahi, const __nv_bfloat16* __restrict__ Alo,
          const __nv_bfloat16* __restrict__ Bhi, const __nv_bfloat16* __restrict__ Blo,
          const float* __restrict__ bias,
          float* __restrict__ C0, float* __restrict__ C1, float* __restrict__ C2)
{
    extern __shared__ char smem[];
    const uint32_t sb = smem_u32(smem);
    const int tid  = threadIdx.x;
    const int lane = tid & 31, wid = tid >> 5;
    const int wm   = wid & 1,  wn  = wid >> 1;
    const int m0   = blockIdx.y * 64;
    const int n0   = blockIdx.x * 128;
    const int w    = blockIdx.x >> 1;
    const int col0 = (blockIdx.x & 1) * 128;
    float* C = (w == 0) ? C0 : ((w == 1) ? C1 : C2);

    const uint32_t xm   = (uint32_t)(lane & 7) << 4;
    const uint32_t aRow = wm * 32 + (lane & 15);
    const uint32_t aK   = (uint32_t)(lane >> 4) * 16;
    const uint32_t bRow = wn * 32 + (uint32_t)(lane >> 4) * 8 + (lane & 7);
    const uint32_t bK   = (uint32_t)((lane >> 3) & 1) * 16;

    float acc[2][4][4];
    #pragma unroll
    for (int mt = 0; mt < 2; mt++)
        #pragma unroll
        for (int nt = 0; nt < 4; nt++)
            #pragma unroll
            for (int i = 0; i < 4; i++) acc[mt][nt][i] = 0.f;

    auto stage = [&](int c, uint32_t base) {
        #pragma unroll
        for (int j = 0; j < 2; j++) {
            int idx = tid + j * 256;
            int row = idx >> 3, kc = idx & 7;
            uint32_t off = (uint32_t)row * 128 +
                           (uint32_t)((kc * 16) ^ ((row & 7) << 4));
            const size_t goff = (size_t)(m0 + row) * C_ + c * 64 + kc * 8;
            CPA(base + PL_AHI + off, Ahi + goff);
            CPA(base + PL_ALO + off, Alo + goff);
        }
        #pragma unroll
        for (int j = 0; j < 4; j++) {
            int idx = tid + j * 256;
            int row = idx >> 3, kc = idx & 7;
            uint32_t off = (uint32_t)row * 128 +
                           (uint32_t)((kc * 16) ^ ((row & 7) << 4));
            const size_t goff = (size_t)(n0 + row) * C_ + c * 64 + kc * 8;
            CPA(base + PL_BHI + off, Bhi + goff);
            CPA(base + PL_BLO + off, Blo + goff);
        }
    };

    stage(0, sb);
    CPCOMMIT();

    for (int c = 0; c < 4; c++) {
        if (c + 1 < 4) {
            stage(c + 1, sb + (uint32_t)((c + 1) & 1) * STAGE_SZ);
            CPCOMMIT();
            CPWAIT(1);
        } else {
            CPWAIT(0);
        }
        __syncthreads();

        const uint32_t base = sb + (uint32_t)(c & 1) * STAGE_SZ;
        #pragma unroll
        for (int kt = 0; kt < 4; kt++) {
            const uint32_t kx  = ((aK + (uint32_t)kt * 32) ^ xm);
            const uint32_t kbx = ((bK + (uint32_t)kt * 32) ^ xm);
            uint32_t a[2][4], bh[4][2], bl[4][2];
            #pragma unroll
            for (int mt = 0; mt < 2; mt++)
                LDSM4(a[mt], base + PL_AHI + (aRow + mt * 16) * 128 + kx);
            #pragma unroll
            for (int p = 0; p < 2; p++) {
                uint32_t off = (bRow + p * 16) * 128 + kbx;
                uint32_t t[4];
                LDSM4(t, base + PL_BHI + off);
                bh[2*p][0] = t[0]; bh[2*p][1] = t[1];
                bh[2*p+1][0] = t[2]; bh[2*p+1][1] = t[3];
                LDSM4(t, base + PL_BLO + off);
                bl[2*p][0] = t[0]; bl[2*p][1] = t[1];
                bl[2*p+1][0] = t[2]; bl[2*p+1][1] = t[3];
            }
            #pragma unroll
            for (int mt = 0; mt < 2; mt++)
                #pragma unroll
                for (int nt = 0; nt < 4; nt++) {
                    MMA(acc[mt][nt], a[mt], bh[nt]);
                    MMA(acc[mt][nt], a[mt], bl[nt]);
                }
            #pragma unroll
            for (int mt = 0; mt < 2; mt++)
                LDSM4(a[mt], base + PL_ALO + (aRow + mt * 16) * 128 + kx);
            #pragma unroll
            for (int mt = 0; mt < 2; mt++)
                #pragma unroll
                for (int nt = 0; nt < 4; nt++)
                    MMA(acc[mt][nt], a[mt], bh[nt]);
        }
        __syncthreads();
    }

    const int rowb = m0 + wm * 32 + (lane >> 2);
    const int colb = col0 + wn * 32 + (lane & 3) * 2;
    #pragma unroll
    for (int nt = 0; nt < 4; nt++) {
        const int col = colb + nt * 8;
        float2 bv = make_float2(0.f, 0.f);
        if (bias) bv = *(const float2*)(bias + col);
        #pragma unroll
        for (int mt = 0; mt < 2; mt++) {
            float2 v0 = make_float2(acc[mt][nt][0] + bv.x, acc[mt][nt][1] + bv.y);
            float2 v1 = make_float2(acc[mt][nt][2] + bv.x, acc[mt][nt][3] + bv.y);
            *(float2*)(C + (size_t)(rowb + mt * 16) * C_ + col)     = v0;
            *(float2*)(C + (size_t)(rowb + mt * 16 + 8) * C_ + col) = v1;
        }
    }
}

// ---------------- K-only focus nonlinearity + fused kmean ----------------------
__global__ void focus_kernel(const float* __restrict__ pos_enc)
{
    __shared__ float kpart[256];
    const int lane = threadIdx.x & 31;
    const int warp = threadIdx.x >> 5;
    const int row  = blockIdx.x * 8 + warp;
    const int n    = row & (N_ - 1);
    const int b    = row >> 12;
    float* krow = g_K + row * C_;
    const float* prow = pos_enc + n * C_;

    kpart[threadIdx.x] = 0.f;
    __syncthreads();

    float tk3[8];
    float sk2 = 0.f, sk6 = 0.f;
    #pragma unroll
    for (int j = 0; j < 8; j++) {
        int c = lane + j * 32;
        float rs = g_rscale[c];
        float k = fmaxf(krow[c] + prow[c], 0.f);
        k = (k + 1e-6f) * rs;
        float k3 = k * k * k;
        sk2 += k * k; sk6 += k3 * k3; tk3[j] = k3;
    }
    #pragma unroll
    for (int off = 16; off > 0; off >>= 1) {
        sk2 += __shfl_xor_sync(0xffffffffu, sk2, off);
        sk6 += __shfl_xor_sync(0xffffffffu, sk6, off);
    }
    float kf = sqrtf(sk2 / sk6);
    #pragma unroll
    for (int j = 0; j < 8; j++) {
        int c = lane + j * 32;
        float kv = tk3[j] * kf;
        krow[c] = kv;
        atomicAdd(&kpart[c], kv);
    }
    __syncthreads();
    if (warp == 0) {
        #pragma unroll
        for (int j = 0; j < 8; j++) {
            int c = lane + j * 32;
            atomicAdd(&g_kmean[b * C_ + c], kpart[c] * (1.f / (float)N_));
        }
    }
}

// kvmat[b,h,d,e] = sum_n K[b,n,h,d]*V[b,n,h,e] / N — 32-row tiles
__global__ void kvmat_kernel()
{
    const int bh = blockIdx.y;
    const int b  = bh >> 3, h = bh & 7;
    const int ns = blockIdx.x;
    const int t  = threadIdx.x;
    const int d  = t & 31, eg = t >> 5;
    __shared__ float ks[32][32], vs[32][32];
    float a0 = 0.f, a1 = 0.f, a2 = 0.f, a3 = 0.f;
    const int base = (b * N_ + ns * 512) * C_ + h * HD;

    for (int cc = 0; cc < 16; cc++) {
        const int off = base + cc * 32 * C_;
        #pragma unroll
        for (int j = 0; j < 4; j++) {
            int idx = t + j * 256;
            int nn = idx >> 5, c = idx & 31;
            ks[nn][c] = g_K[off + nn * C_ + c];
            vs[nn][c] = g_V[off + nn * C_ + c];
        }
        __syncthreads();
        #pragma unroll
        for (int nn = 0; nn < 32; nn++) {
            float  kd = ks[nn][d];
            float4 v4 = *(const float4*)&vs[nn][eg * 4];
            a0 += kd * v4.x; a1 += kd * v4.y; a2 += kd * v4.z; a3 += kd * v4.w;
        }
        __syncthreads();
    }
    const float sc = 1.f / (float)N_;
    const int  o  = (bh * HD + d) * HD + eg * 4;
    atomicAdd(&g_kvmat[o + 0], a0 * sc);
    atomicAdd(&g_kvmat[o + 1], a1 * sc);
    atomicAdd(&g_kvmat[o + 2], a2 * sc);
    atomicAdd(&g_kvmat[o + 3], a3 * sc);
}

// attn with fused Q-focus: q_s holds t3 = ((relu(q)+eps)*rscale)^3; per-row
// factors qf = sqrt(sum t2 / sum t6) reduced via warp shuffles + smem atomics.
// out = qf*acc / (qf*s_z + eps) — algebraically identical to the reference.
__global__ __launch_bounds__(256, 1)
void attn_kernel()
{
    extern __shared__ float sm[];
    float* q_s    = sm;                       // 256*33
    float* kvs    = q_s + 256 * 33;           // 8192
    float* km     = kvs + NH * HD * HD;       // 256
    float* o_s    = km + 256;                 // 32*257
    float* rowsum = o_s + 32 * 257;           // 32*2 (sum2, sum6)

    const int b    = blockIdx.y;
    const int tile = blockIdx.x;
    const int row0 = b * N_ + tile * 32;
    const int t    = threadIdx.x;
    const int lane = t & 31;

    if (t < 64) rowsum[t] = 0.f;
    __syncthreads();

    const float rs = g_rscale[t];
    #pragma unroll
    for (int j = 0; j < 32; j++) {
        float v = fmaxf(g_Q[(row0 + j) * C_ + t], 0.f);
        v = (v + 1e-6f) * rs;
        float v3 = v * v * v;
        q_s[t * 33 + j] = v3;
        float a2 = v * v, a6 = v3 * v3;
        #pragma unroll
        for (int off = 16; off > 0; off >>= 1) {
            a2 += __shfl_xor_sync(0xffffffffu, a2, off);
            a6 += __shfl_xor_sync(0xffffffffu, a6, off);
        }
        if (lane == 0) {
            atomicAdd(&rowsum[j * 2],     a2);
            atomicAdd(&rowsum[j * 2 + 1], a6);
        }
    }
    for (int j = t; j < NH * HD * HD; j += 256)
        kvs[j] = g_kvmat[b * NH * HD * HD + j];
    km[t] = g_kmean[b * C_ + t];
    __syncthreads();

    const int n = t & 31, h = t >> 5;
    const float qf = sqrtf(rowsum[n * 2] / rowsum[n * 2 + 1]);
    float qv[32];
    float s_z = 0.f;
    #pragma unroll
    for (int d = 0; d < 32; d++) {
        qv[d] = q_s[(h * HD + d) * 33 + n];
        s_z += qv[d] * km[h * HD + d];
    }
    float acc[32];
    #pragma unroll
    for (int e = 0; e < 32; e++) acc[e] = 0.f;
    const float* kvh = kvs + h * HD * HD;
    #pragma unroll 4
    for (int d = 0; d < 32; d++) {
        float qd = qv[d];
        #pragma unroll
        for (int e4 = 0; e4 < 8; e4++) {
            float4 kv = *(const float4*)&kvh[d * HD + e4 * 4];
            acc[e4*4+0] += qd * kv.x;
            acc[e4*4+1] += qd * kv.y;
            acc[e4*4+2] += qd * kv.z;
            acc[e4*4+3] += qd * kv.w;
        }
    }
    float fac = qf / (qf * s_z + 1e-6f);
    #pragma unroll
    for (int e = 0; e < 32; e++)
        o_s[n * 257 + h * HD + e] = acc[e] * fac;
    __syncthreads();
    #pragma unroll
    for (int j = 0; j < 32; j++)
        g_O[(row0 + j) * C_ + t] = o_s[j * 257 + t];
}

// dwconv — exact R13 version
__global__ void dwconv_kernel(const float* __restrict__ Wc,
                              const float* __restrict__ bc)
{
    const int c  = threadIdx.x;
    const int y  = blockIdx.x;
    const int b  = blockIdx.y;
    const int ch = c & (HD - 1);
    float w[25];
    #pragma unroll
    for (int i = 0; i < 25; i++) w[i] = Wc[ch * 25 + i];
    const float bias = bc[ch];

    const float* vb = g_V + (b * N_) * C_ + c;
    const float* ob = g_O + (b * N_) * C_ + c;
    __nv_bfloat16* ph = g_ohi + (size_t)(b * N_) * C_ + c;
    __nv_bfloat16* pl = g_olo + (size_t)(b * N_) * C_ + c;

    float win[5][5];
    #pragma unroll
    for (int wy = 0; wy < 5; wy++) {
        int Y = y + wy - 2;
        bool yin = (Y >= 0) && (Y < 64);
        #pragma unroll
        for (int wx = 0; wx < 5; wx++) {
            int X = wx - 2;
            win[wy][wx] = (yin && X >= 0) ? vb[(Y * 64 + X) * C_] : 0.f;
        }
    }
    for (int x = 0; x < 64; x++) {
        float acc = bias;
        #pragma unroll
        for (int wy = 0; wy < 5; wy++)
            #pragma unroll
            for (int wx = 0; wx < 5; wx++)
                acc += win[wy][wx] * w[wy * 5 + wx];
        float val = ob[(y * 64 + x) * C_] + acc;
        __nv_bfloat16 h = __float2bfloat16_rn(val);
        __nv_bfloat16 l = __float2bfloat16_rn(val - __bfloat162float(h));
        ph[(y * 64 + x) * C_] = h;
        pl[(y * 64 + x) * C_] = l;
        #pragma unroll
        for (int wy = 0; wy < 5; wy++)
            #pragma unroll
            for (int wx = 0; wx < 4; wx++) win[wy][wx] = win[wy][wx + 1];
        int X = x + 3;
        bool xin = X < 64;
        #pragma unroll
        for (int wy = 0; wy < 5; wy++) {
            int Y = y + wy - 2;
            win[wy][4] = (xin && Y >= 0 && Y < 64) ? vb[(Y * 64 + X) * C_] : 0.f;
        }
    }
}

// ------------------------------- host launcher -------------------------------
extern "C" void kernel_launch(void* const* d_in, const int* in_sizes, int n_in,
                              void* d_out, int out_size)
{
    const float* x     = (const float*)d_in[0];
    const float* Wq    = (const float*)d_in[1];
    const float* Wkv   = (const float*)d_in[2];
    const float* Wp    = (const float*)d_in[3];
    const float* bp    = (const float*)d_in[4];
    const float* scale = (const float*)d_in[5];
    const float* pos   = (const float*)d_in[6];
    const float* dwcw  = (const float*)d_in[7];
    const float* dwcb  = (const float*)d_in[8];
    float* out = (float*)d_out;

    float *Qp, *Kp, *Vp, *Op;
    __nv_bfloat16 *xhi, *xlo, *ohi, *olo, *whi, *wlo;
    cudaGetSymbolAddress((void**)&Qp,  g_Q);
    cudaGetSymbolAddress((void**)&Kp,  g_K);
    cudaGetSymbolAddress((void**)&Vp,  g_V);
    cudaGetSymbolAddress((void**)&Op,  g_O);
    cudaGetSymbolAddress((void**)&xhi, g_xhi);
    cudaGetSymbolAddress((void**)&xlo, g_xlo);
    cudaGetSymbolAddress((void**)&ohi, g_ohi);
    cudaGetSymbolAddress((void**)&olo, g_olo);
    cudaGetSymbolAddress((void**)&whi, g_whi);
    cudaGetSymbolAddress((void**)&wlo, g_wlo);

    const int ATTN_SMEM = (256 * 33 + NH * HD * HD + 256 + 32 * 257 + 64) * 4;
    static bool attr_done = false;
    if (!attr_done) {
        cudaFuncSetAttribute(attn_kernel,
                             cudaFuncAttributeMaxDynamicSharedMemorySize, ATTN_SMEM);
        cudaFuncSetAttribute(gemm_hmma,
                             cudaFuncAttributeMaxDynamicSharedMemorySize, SM_GTOT);
        attr_done = true;
    }

    const int WS = C_ * C_;

    cvt_hilo_kernel<<<(M_ * C_ / 4 + 255) / 256, 256>>>(x, xhi, xlo, M_ * C_ / 4);
    prep_w_kernel<<<dim3(C_, 4), 256>>>(Wq, Wkv, Wp);
    prep_scale_zero_kernel<<<(B_ * NH * HD * HD + 255) / 256, 256>>>(scale);

    gemm_hmma<<<dim3(6, M_ / 64), 256, SM_GTOT>>>(xhi, xlo, whi, wlo,
                                                  nullptr, Qp, Kp, Vp);

    focus_kernel<<<M_ / 8, 256>>>(pos);

    kvmat_kernel<<<dim3(8, B_ * NH), 256>>>();

    attn_kernel<<<dim3(N_ / 32, B_), 256, ATTN_SMEM>>>();

    dwconv_kernel<<<dim3(64, B_), 256>>>(dwcw, dwcb);

    gemm_hmma<<<dim3(2, M_ / 64), 256, SM_GTOT>>>(ohi, olo,
                                                  whi + 3 * WS, wlo + 3 * WS,
                                                  bp, out, out, out);
}

// round 15
// speedup vs baseline: 1.0696x; 1.0696x over previous
#include <cuda_runtime.h>
#include <cuda_bf16.h>
#include <cstdint>

#define B_   16
#define N_   4096
#define C_   256
#define NH   8
#define HD   32
#define M_   (B_ * N_)

// ---------------- scratch ----------------
__device__ __align__(16) float g_Q[M_ * C_];
__device__ __align__(16) float g_K[M_ * C_];
__device__ __align__(16) float g_V[M_ * C_];
__device__ __align__(16) float g_O[M_ * C_];
__device__ __align__(16) float g_kmean[B_ * C_];
__device__ __align__(16) float g_kvmat[B_ * NH * HD * HD];
__device__ __align__(16) float g_rscale[C_];
__device__ __align__(16) __nv_bfloat16 g_xhi[M_ * C_];
__device__ __align__(16) __nv_bfloat16 g_xlo[M_ * C_];
__device__ __align__(16) __nv_bfloat16 g_ohi[M_ * C_];
__device__ __align__(16) __nv_bfloat16 g_olo[M_ * C_];
__device__ __align__(16) __nv_bfloat16 g_whi[4 * C_ * C_];   // [w][n][k]
__device__ __align__(16) __nv_bfloat16 g_wlo[4 * C_ * C_];

// ---------------- helpers ----------------
__device__ __forceinline__ uint32_t smem_u32(const void* p) {
    uint32_t a;
    asm("{ .reg .u64 t; cvta.to.shared.u64 t, %1; cvt.u32.u64 %0, t; }"
        : "=r"(a) : "l"(p));
    return a;
}
#define CPA(dst, src) \
    asm volatile("cp.async.cg.shared.global [%0], [%1], 16;" \
                 :: "r"(dst), "l"(__cvta_generic_to_global(src)) : "memory")
#define CPCOMMIT() asm volatile("cp.async.commit_group;" ::: "memory")
#define CPWAIT(n)  asm volatile("cp.async.wait_group %0;" :: "n"(n) : "memory")

#define LDSM4(d, addr) \
    asm volatile("ldmatrix.sync.aligned.m8n8.x4.shared.b16 {%0,%1,%2,%3}, [%4];" \
        : "=r"((d)[0]), "=r"((d)[1]), "=r"((d)[2]), "=r"((d)[3]) : "r"(addr))

#define MMA(c, a, b) \
    asm volatile("mma.sync.aligned.m16n8k16.row.col.f32.bf16.bf16.f32 " \
        "{%0,%1,%2,%3}, {%4,%5,%6,%7}, {%8,%9}, {%0,%1,%2,%3};" \
        : "+f"((c)[0]), "+f"((c)[1]), "+f"((c)[2]), "+f"((c)[3]) \
        : "r"((a)[0]), "r"((a)[1]), "r"((a)[2]), "r"((a)[3]), \
          "r"((b)[0]), "r"((b)[1]))

// ---------------- hi/lo conversion ----------------
union BF2U { __nv_bfloat162 b; uint32_t u; };
__device__ __forceinline__ void cvt4(float4 v, uint2& hi, uint2& lo) {
    __nv_bfloat16 h0 = __float2bfloat16_rn(v.x), h1 = __float2bfloat16_rn(v.y);
    __nv_bfloat16 h2 = __float2bfloat16_rn(v.z), h3 = __float2bfloat16_rn(v.w);
    __nv_bfloat16 l0 = __float2bfloat16_rn(v.x - __bfloat162float(h0));
    __nv_bfloat16 l1 = __float2bfloat16_rn(v.y - __bfloat162float(h1));
    __nv_bfloat16 l2 = __float2bfloat16_rn(v.z - __bfloat162float(h2));
    __nv_bfloat16 l3 = __float2bfloat16_rn(v.w - __bfloat162float(h3));
    BF2U a, b;
    a.b = __halves2bfloat162(h0, h1); b.b = __halves2bfloat162(h2, h3);
    hi = make_uint2(a.u, b.u);
    a.b = __halves2bfloat162(l0, l1); b.b = __halves2bfloat162(l2, l3);
    lo = make_uint2(a.u, b.u);
}

__global__ void cvt_hilo_kernel(const float* __restrict__ src,
                                __nv_bfloat16* __restrict__ hi,
                                __nv_bfloat16* __restrict__ lo, int n4)
{
    int i = blockIdx.x * 256 + threadIdx.x;
    if (i >= n4) return;
    float4 v = ((const float4*)src)[i];
    uint2 h, l;
    cvt4(v, h, l);
    ((uint2*)hi)[i] = h;
    ((uint2*)lo)[i] = l;
}

__global__ void prep_w_kernel(const float* __restrict__ Wq,
                              const float* __restrict__ Wkv,
                              const float* __restrict__ Wp)
{
    int k = blockIdx.x, w = blockIdx.y, n = threadIdx.x;
    float v;
    if      (w == 0) v = Wq[k * C_ + n];
    else if (w == 1) v = Wkv[k * 2 * C_ + n];
    else if (w == 2) v = Wkv[k * 2 * C_ + C_ + n];
    else             v = Wp[k * C_ + n];
    __nv_bfloat16 h = __float2bfloat16_rn(v);
    __nv_bfloat16 l = __float2bfloat16_rn(v - __bfloat162float(h));
    g_whi[(w * C_ + n) * C_ + k] = h;
    g_wlo[(w * C_ + n) * C_ + k] = l;
}

// precompute 1/softplus(scale_param); also zero kmean+kvmat accumulators
__global__ void prep_scale_zero_kernel(const float* __restrict__ scale_param)
{
    int t = blockIdx.x * 256 + threadIdx.x;
    if (blockIdx.x == 0) {
        float sp = scale_param[t];
        float s  = (sp > 20.f) ? sp : log1pf(expf(sp));
        g_rscale[t] = 1.f / s;
    }
    if (t < B_ * C_) g_kmean[t] = 0.f;
    if (t < B_ * NH * HD * HD) g_kvmat[t] = 0.f;
}

// ---------------- HMMA split-precision GEMM, 64x128 tile, 2 CTA/SM ------------
#define STAGE_SZ 49152
#define PL_AHI 0
#define PL_ALO 8192
#define PL_BHI 16384
#define PL_BLO 32768
#define SM_GTOT (2 * STAGE_SZ)

__global__ void __launch_bounds__(256, 2)
gemm_hmma(const __nv_bfloat16* __restrict__ Ahi, const __nv_bfloat16* __restrict__ Alo,
          const __nv_bfloat16* __restrict__ Bhi, const __nv_bfloat16* __restrict__ Blo,
          const float* __restrict__ bias,
          float* __restrict__ C0, float* __restrict__ C1, float* __restrict__ C2)
{
    extern __shared__ char smem[];
    const uint32_t sb = smem_u32(smem);
    const int tid  = threadIdx.x;
    const int lane = tid & 31, wid = tid >> 5;
    const int wm   = wid & 1,  wn  = wid >> 1;
    const int m0   = blockIdx.y * 64;
    const int n0   = blockIdx.x * 128;
    const int w    = blockIdx.x >> 1;
    const int col0 = (blockIdx.x & 1) * 128;
    float* C = (w == 0) ? C0 : ((w == 1) ? C1 : C2);

    const uint32_t xm   = (uint32_t)(lane & 7) << 4;
    const uint32_t aRow = wm * 32 + (lane & 15);
    const uint32_t aK   = (uint32_t)(lane >> 4) * 16;
    const uint32_t bRow = wn * 32 + (uint32_t)(lane >> 4) * 8 + (lane & 7);
    const uint32_t bK   = (uint32_t)((lane >> 3) & 1) * 16;

    float acc[2][4][4];
    #pragma unroll
    for (int mt = 0; mt < 2; mt++)
        #pragma unroll
        for (int nt = 0; nt < 4; nt++)
            #pragma unroll
            for (int i = 0; i < 4; i++) acc[mt][nt][i] = 0.f;

    auto stage = [&](int c, uint32_t base) {
        #pragma unroll
        for (int j = 0; j < 2; j++) {
            int idx = tid + j * 256;
            int row = idx >> 3, kc = idx & 7;
            uint32_t off = (uint32_t)row * 128 +
                           (uint32_t)((kc * 16) ^ ((row & 7) << 4));
            const size_t goff = (size_t)(m0 + row) * C_ + c * 64 + kc * 8;
            CPA(base + PL_AHI + off, Ahi + goff);
            CPA(base + PL_ALO + off, Alo + goff);
        }
        #pragma unroll
        for (int j = 0; j < 4; j++) {
            int idx = tid + j * 256;
            int row = idx >> 3, kc = idx & 7;
            uint32_t off = (uint32_t)row * 128 +
                           (uint32_t)((kc * 16) ^ ((row & 7) << 4));
            const size_t goff = (size_t)(n0 + row) * C_ + c * 64 + kc * 8;
            CPA(base + PL_BHI + off, Bhi + goff);
            CPA(base + PL_BLO + off, Blo + goff);
        }
    };

    stage(0, sb);
    CPCOMMIT();

    for (int c = 0; c < 4; c++) {
        if (c + 1 < 4) {
            stage(c + 1, sb + (uint32_t)((c + 1) & 1) * STAGE_SZ);
            CPCOMMIT();
            CPWAIT(1);
        } else {
            CPWAIT(0);
        }
        __syncthreads();

        const uint32_t base = sb + (uint32_t)(c & 1) * STAGE_SZ;
        #pragma unroll
        for (int kt = 0; kt < 4; kt++) {
            const uint32_t kx  = ((aK + (uint32_t)kt * 32) ^ xm);
            const uint32_t kbx = ((bK + (uint32_t)kt * 32) ^ xm);
            uint32_t a[2][4], bh[4][2], bl[4][2];
            #pragma unroll
            for (int mt = 0; mt < 2; mt++)
                LDSM4(a[mt], base + PL_AHI + (aRow + mt * 16) * 128 + kx);
            #pragma unroll
            for (int p = 0; p < 2; p++) {
                uint32_t off = (bRow + p * 16) * 128 + kbx;
                uint32_t t[4];
                LDSM4(t, base + PL_BHI + off);
                bh[2*p][0] = t[0]; bh[2*p][1] = t[1];
                bh[2*p+1][0] = t[2]; bh[2*p+1][1] = t[3];
                LDSM4(t, base + PL_BLO + off);
                bl[2*p][0] = t[0]; bl[2*p][1] = t[1];
                bl[2*p+1][0] = t[2]; bl[2*p+1][1] = t[3];
            }
            #pragma unroll
            for (int mt = 0; mt < 2; mt++)
                #pragma unroll
                for (int nt = 0; nt < 4; nt++) {
                    MMA(acc[mt][nt], a[mt], bh[nt]);
                    MMA(acc[mt][nt], a[mt], bl[nt]);
                }
            #pragma unroll
            for (int mt = 0; mt < 2; mt++)
                LDSM4(a[mt], base + PL_ALO + (aRow + mt * 16) * 128 + kx);
            #pragma unroll
            for (int mt = 0; mt < 2; mt++)
                #pragma unroll
                for (int nt = 0; nt < 4; nt++)
                    MMA(acc[mt][nt], a[mt], bh[nt]);
        }
        __syncthreads();
    }

    const int rowb = m0 + wm * 32 + (lane >> 2);
    const int colb = col0 + wn * 32 + (lane & 3) * 2;
    #pragma unroll
    for (int nt = 0; nt < 4; nt++) {
        const int col = colb + nt * 8;
        float2 bv = make_float2(0.f, 0.f);
        if (bias) bv = *(const float2*)(bias + col);
        #pragma unroll
        for (int mt = 0; mt < 2; mt++) {
            float2 v0 = make_float2(acc[mt][nt][0] + bv.x, acc[mt][nt][1] + bv.y);
            float2 v1 = make_float2(acc[mt][nt][2] + bv.x, acc[mt][nt][3] + bv.y);
            *(float2*)(C + (size_t)(rowb + mt * 16) * C_ + col)     = v0;
            *(float2*)(C + (size_t)(rowb + mt * 16 + 8) * C_ + col) = v1;
        }
    }
}

// ---------------- K-only focus nonlinearity + fused kmean ----------------------
__global__ void focus_kernel(const float* __restrict__ pos_enc)
{
    __shared__ float kpart[256];
    const int lane = threadIdx.x & 31;
    const int warp = threadIdx.x >> 5;
    const int row  = blockIdx.x * 8 + warp;
    const int n    = row & (N_ - 1);
    const int b    = row >> 12;
    float* krow = g_K + row * C_;
    const float* prow = pos_enc + n * C_;

    kpart[threadIdx.x] = 0.f;
    __syncthreads();

    float tk3[8];
    float sk2 = 0.f, sk6 = 0.f;
    #pragma unroll
    for (int j = 0; j < 8; j++) {
        int c = lane + j * 32;
        float rs = g_rscale[c];
        float k = fmaxf(krow[c] + prow[c], 0.f);
        k = (k + 1e-6f) * rs;
        float k3 = k * k * k;
        sk2 += k * k; sk6 += k3 * k3; tk3[j] = k3;
    }
    #pragma unroll
    for (int off = 16; off > 0; off >>= 1) {
        sk2 += __shfl_xor_sync(0xffffffffu, sk2, off);
        sk6 += __shfl_xor_sync(0xffffffffu, sk6, off);
    }
    float kf = sqrtf(sk2 / sk6);
    #pragma unroll
    for (int j = 0; j < 8; j++) {
        int c = lane + j * 32;
        float kv = tk3[j] * kf;
        krow[c] = kv;
        atomicAdd(&kpart[c], kv);
    }
    __syncthreads();
    if (warp == 0) {
        #pragma unroll
        for (int j = 0; j < 8; j++) {
            int c = lane + j * 32;
            atomicAdd(&g_kmean[b * C_ + c], kpart[c] * (1.f / (float)N_));
        }
    }
}

// kvmat[b,h,d,e] = sum_n K[b,n,h,d]*V[b,n,h,e] / N — 32-row tiles
__global__ void kvmat_kernel()
{
    const int bh = blockIdx.y;
    const int b  = bh >> 3, h = bh & 7;
    const int ns = blockIdx.x;
    const int t  = threadIdx.x;
    const int d  = t & 31, eg = t >> 5;
    __shared__ float ks[32][32], vs[32][32];
    float a0 = 0.f, a1 = 0.f, a2 = 0.f, a3 = 0.f;
    const int base = (b * N_ + ns * 512) * C_ + h * HD;

    for (int cc = 0; cc < 16; cc++) {
        const int off = base + cc * 32 * C_;
        #pragma unroll
        for (int j = 0; j < 4; j++) {
            int idx = t + j * 256;
            int nn = idx >> 5, c = idx & 31;
            ks[nn][c] = g_K[off + nn * C_ + c];
            vs[nn][c] = g_V[off + nn * C_ + c];
        }
        __syncthreads();
        #pragma unroll
        for (int nn = 0; nn < 32; nn++) {
            float  kd = ks[nn][d];
            float4 v4 = *(const float4*)&vs[nn][eg * 4];
            a0 += kd * v4.x; a1 += kd * v4.y; a2 += kd * v4.z; a3 += kd * v4.w;
        }
        __syncthreads();
    }
    const float sc = 1.f / (float)N_;
    const int  o  = (bh * HD + d) * HD + eg * 4;
    atomicAdd(&g_kvmat[o + 0], a0 * sc);
    atomicAdd(&g_kvmat[o + 1], a1 * sc);
    atomicAdd(&g_kvmat[o + 2], a2 * sc);
    atomicAdd(&g_kvmat[o + 3], a3 * sc);
}

// attn with fused Q-focus, v2: load phase stores v (plain coalesced LDGs,
// R13-identical structure); row reductions happen in the compute phase where
// the transposed layout makes them register-local + 2 smem atomics/thread.
// out = qf*acc / (qf*s_z + eps) — algebraically identical to the reference.
__global__ __launch_bounds__(256, 1)
void attn_kernel()
{
    extern __shared__ float sm[];
    float* q_s    = sm;                       // 256*33  (stores v)
    float* kvs    = q_s + 256 * 33;           // 8192
    float* km     = kvs + NH * HD * HD;       // 256
    float* o_s    = km + 256;                 // 32*257
    float* rowsum = o_s + 32 * 257;           // 32*2 (sum2, sum6)

    const int b    = blockIdx.y;
    const int tile = blockIdx.x;
    const int row0 = b * N_ + tile * 32;
    const int t    = threadIdx.x;

    if (t < 64) rowsum[t] = 0.f;

    const float rs = g_rscale[t];
    #pragma unroll
    for (int j = 0; j < 32; j++) {
        float v = fmaxf(g_Q[(row0 + j) * C_ + t], 0.f);
        q_s[t * 33 + j] = (v + 1e-6f) * rs;
    }
    for (int j = t; j < NH * HD * HD; j += 256)
        kvs[j] = g_kvmat[b * NH * HD * HD + j];
    km[t] = g_kmean[b * C_ + t];
    __syncthreads();

    const int n = t & 31, h = t >> 5;
    float qv[32];
    float s_z = 0.f, s2 = 0.f, s6 = 0.f;
    #pragma unroll
    for (int d = 0; d < 32; d++) {
        float v  = q_s[(h * HD + d) * 33 + n];
        float v3 = v * v * v;
        qv[d] = v3;
        s2 += v * v;
        s6 += v3 * v3;
        s_z += v3 * km[h * HD + d];
    }
    atomicAdd(&rowsum[n * 2],     s2);
    atomicAdd(&rowsum[n * 2 + 1], s6);

    float acc[32];
    #pragma unroll
    for (int e = 0; e < 32; e++) acc[e] = 0.f;
    const float* kvh = kvs + h * HD * HD;
    #pragma unroll 4
    for (int d = 0; d < 32; d++) {
        float qd = qv[d];
        #pragma unroll
        for (int e4 = 0; e4 < 8; e4++) {
            float4 kv = *(const float4*)&kvh[d * HD + e4 * 4];
            acc[e4*4+0] += qd * kv.x;
            acc[e4*4+1] += qd * kv.y;
            acc[e4*4+2] += qd * kv.z;
            acc[e4*4+3] += qd * kv.w;
        }
    }
    __syncthreads();                      // rowsum complete
    const float qf  = sqrtf(rowsum[n * 2] / rowsum[n * 2 + 1]);
    const float fac = qf / (qf * s_z + 1e-6f);
    #pragma unroll
    for (int e = 0; e < 32; e++)
        o_s[n * 257 + h * HD + e] = acc[e] * fac;
    __syncthreads();
    #pragma unroll
    for (int j = 0; j < 32; j++)
        g_O[(row0 + j) * C_ + t] = o_s[j * 257 + t];
}

// dwconv — exact R13 version
__global__ void dwconv_kernel(const float* __restrict__ Wc,
                              const float* __restrict__ bc)
{
    const int c  = threadIdx.x;
    const int y  = blockIdx.x;
    const int b  = blockIdx.y;
    const int ch = c & (HD - 1);
    float w[25];
    #pragma unroll
    for (int i = 0; i < 25; i++) w[i] = Wc[ch * 25 + i];
    const float bias = bc[ch];

    const float* vb = g_V + (b * N_) * C_ + c;
    const float* ob = g_O + (b * N_) * C_ + c;
    __nv_bfloat16* ph = g_ohi + (size_t)(b * N_) * C_ + c;
    __nv_bfloat16* pl = g_olo + (size_t)(b * N_) * C_ + c;

    float win[5][5];
    #pragma unroll
    for (int wy = 0; wy < 5; wy++) {
        int Y = y + wy - 2;
        bool yin = (Y >= 0) && (Y < 64);
        #pragma unroll
        for (int wx = 0; wx < 5; wx++) {
            int X = wx - 2;
            win[wy][wx] = (yin && X >= 0) ? vb[(Y * 64 + X) * C_] : 0.f;
        }
    }
    for (int x = 0; x < 64; x++) {
        float acc = bias;
        #pragma unroll
        for (int wy = 0; wy < 5; wy++)
            #pragma unroll
            for (int wx = 0; wx < 5; wx++)
                acc += win[wy][wx] * w[wy * 5 + wx];
        float val = ob[(y * 64 + x) * C_] + acc;
        __nv_bfloat16 h = __float2bfloat16_rn(val);
        __nv_bfloat16 l = __float2bfloat16_rn(val - __bfloat162float(h));
        ph[(y * 64 + x) * C_] = h;
        pl[(y * 64 + x) * C_] = l;
        #pragma unroll
        for (int wy = 0; wy < 5; wy++)
            #pragma unroll
            for (int wx = 0; wx < 4; wx++) win[wy][wx] = win[wy][wx + 1];
        int X = x + 3;
        bool xin = X < 64;
        #pragma unroll
        for (int wy = 0; wy < 5; wy++) {
            int Y = y + wy - 2;
            win[wy][4] = (xin && Y >= 0 && Y < 64) ? vb[(Y * 64 + X) * C_] : 0.f;
        }
    }
}

// ------------------------------- host launcher -------------------------------
extern "C" void kernel_launch(void* const* d_in, const int* in_sizes, int n_in,
                              void* d_out, int out_size)
{
    const float* x     = (const float*)d_in[0];
    const float* Wq    = (const float*)d_in[1];
    const float* Wkv   = (const float*)d_in[2];
    const float* Wp    = (const float*)d_in[3];
    const float* bp    = (const float*)d_in[4];
    const float* scale = (const float*)d_in[5];
    const float* pos   = (const float*)d_in[6];
    const float* dwcw  = (const float*)d_in[7];
    const float* dwcb  = (const float*)d_in[8];
    float* out = (float*)d_out;

    float *Qp, *Kp, *Vp, *Op;
    __nv_bfloat16 *xhi, *xlo, *ohi, *olo, *whi, *wlo;
    cudaGetSymbolAddress((void**)&Qp,  g_Q);
    cudaGetSymbolAddress((void**)&Kp,  g_K);
    cudaGetSymbolAddress((void**)&Vp,  g_V);
    cudaGetSymbolAddress((void**)&Op,  g_O);
    cudaGetSymbolAddress((void**)&xhi, g_xhi);
    cudaGetSymbolAddress((void**)&xlo, g_xlo);
    cudaGetSymbolAddress((void**)&ohi, g_ohi);
    cudaGetSymbolAddress((void**)&olo, g_olo);
    cudaGetSymbolAddress((void**)&whi, g_whi);
    cudaGetSymbolAddress((void**)&wlo, g_wlo);

    const int ATTN_SMEM = (256 * 33 + NH * HD * HD + 256 + 32 * 257 + 64) * 4;
    static bool attr_done = false;
    if (!attr_done) {
        cudaFuncSetAttribute(attn_kernel,
                             cudaFuncAttributeMaxDynamicSharedMemorySize, ATTN_SMEM);
        cudaFuncSetAttribute(gemm_hmma,
                             cudaFuncAttributeMaxDynamicSharedMemorySize, SM_GTOT);
        attr_done = true;
    }

    const int WS = C_ * C_;

    cvt_hilo_kernel<<<(M_ * C_ / 4 + 255) / 256, 256>>>(x, xhi, xlo, M_ * C_ / 4);
    prep_w_kernel<<<dim3(C_, 4), 256>>>(Wq, Wkv, Wp);
    prep_scale_zero_kernel<<<(B_ * NH * HD * HD + 255) / 256, 256>>>(scale);

    gemm_hmma<<<dim3(6, M_ / 64), 256, SM_GTOT>>>(xhi, xlo, whi, wlo,
                                                  nullptr, Qp, Kp, Vp);

    focus_kernel<<<M_ / 8, 256>>>(pos);

    kvmat_kernel<<<dim3(8, B_ * NH), 256>>>();

    attn_kernel<<<dim3(N_ / 32, B_), 256, ATTN_SMEM>>>();

    dwconv_kernel<<<dim3(64, B_), 256>>>(dwcw, dwcb);

    gemm_hmma<<<dim3(2, M_ / 64), 256, SM_GTOT>>>(ohi, olo,
                                                  whi + 3 * WS, wlo + 3 * WS,
                                                  bp, out, out, out);
}

// round 16
// speedup vs baseline: 1.0806x; 1.0103x over previous
#include <cuda_runtime.h>
#include <cuda_bf16.h>
#include <cstdint>

#define B_   16
#define N_   4096
#define C_   256
#define NH   8
#define HD   32
#define M_   (B_ * N_)

// ---------------- scratch ----------------
__device__ __align__(16) float g_Q[M_ * C_];
__device__ __align__(16) float g_K[M_ * C_];
__device__ __align__(16) float g_V[M_ * C_];
__device__ __align__(16) float g_O[M_ * C_];
__device__ __align__(16) float g_kmean[B_ * C_];
__device__ __align__(16) float g_kvmat[B_ * NH * HD * HD];
__device__ __align__(16) float g_rscale[C_];
__device__ __align__(16) __nv_bfloat16 g_xhi[M_ * C_];
__device__ __align__(16) __nv_bfloat16 g_xlo[M_ * C_];
__device__ __align__(16) __nv_bfloat16 g_ohi[M_ * C_];
__device__ __align__(16) __nv_bfloat16 g_olo[M_ * C_];
__device__ __align__(16) __nv_bfloat16 g_whi[4 * C_ * C_];   // [w][n][k]
__device__ __align__(16) __nv_bfloat16 g_wlo[4 * C_ * C_];

// ---------------- helpers ----------------
__device__ __forceinline__ uint32_t smem_u32(const void* p) {
    uint32_t a;
    asm("{ .reg .u64 t; cvta.to.shared.u64 t, %1; cvt.u32.u64 %0, t; }"
        : "=r"(a) : "l"(p));
    return a;
}
#define CPA(dst, src) \
    asm volatile("cp.async.cg.shared.global [%0], [%1], 16;" \
                 :: "r"(dst), "l"(__cvta_generic_to_global(src)) : "memory")
#define CPCOMMIT() asm volatile("cp.async.commit_group;" ::: "memory")
#define CPWAIT(n)  asm volatile("cp.async.wait_group %0;" :: "n"(n) : "memory")

#define LDSM4(d, addr) \
    asm volatile("ldmatrix.sync.aligned.m8n8.x4.shared.b16 {%0,%1,%2,%3}, [%4];" \
        : "=r"((d)[0]), "=r"((d)[1]), "=r"((d)[2]), "=r"((d)[3]) : "r"(addr))

#define MMA(c, a, b) \
    asm volatile("mma.sync.aligned.m16n8k16.row.col.f32.bf16.bf16.f32 " \
        "{%0,%1,%2,%3}, {%4,%5,%6,%7}, {%8,%9}, {%0,%1,%2,%3};" \
        : "+f"((c)[0]), "+f"((c)[1]), "+f"((c)[2]), "+f"((c)[3]) \
        : "r"((a)[0]), "r"((a)[1]), "r"((a)[2]), "r"((a)[3]), \
          "r"((b)[0]), "r"((b)[1]))

// ---------------- hi/lo conversion ----------------
union BF2U { __nv_bfloat162 b; uint32_t u; };
__device__ __forceinline__ void cvt4(float4 v, uint2& hi, uint2& lo) {
    __nv_bfloat16 h0 = __float2bfloat16_rn(v.x), h1 = __float2bfloat16_rn(v.y);
    __nv_bfloat16 h2 = __float2bfloat16_rn(v.z), h3 = __float2bfloat16_rn(v.w);
    __nv_bfloat16 l0 = __float2bfloat16_rn(v.x - __bfloat162float(h0));
    __nv_bfloat16 l1 = __float2bfloat16_rn(v.y - __bfloat162float(h1));
    __nv_bfloat16 l2 = __float2bfloat16_rn(v.z - __bfloat162float(h2));
    __nv_bfloat16 l3 = __float2bfloat16_rn(v.w - __bfloat162float(h3));
    BF2U a, b;
    a.b = __halves2bfloat162(h0, h1); b.b = __halves2bfloat162(h2, h3);
    hi = make_uint2(a.u, b.u);
    a.b = __halves2bfloat162(l0, l1); b.b = __halves2bfloat162(l2, l3);
    lo = make_uint2(a.u, b.u);
}

__global__ void cvt_hilo_kernel(const float* __restrict__ src,
                                __nv_bfloat16* __restrict__ hi,
                                __nv_bfloat16* __restrict__ lo, int n4)
{
    int i = blockIdx.x * 256 + threadIdx.x;
    if (i >= n4) return;
    float4 v = ((const float4*)src)[i];
    uint2 h, l;
    cvt4(v, h, l);
    ((uint2*)hi)[i] = h;
    ((uint2*)lo)[i] = l;
}

// weight transpose+convert; block column w==0 also zeros accumulators and
// block (0,0) computes rscale = 1/softplus(scale_param).
__global__ void prep_w_kernel(const float* __restrict__ Wq,
                              const float* __restrict__ Wkv,
                              const float* __restrict__ Wp,
                              const float* __restrict__ scale_param)
{
    int k = blockIdx.x, w = blockIdx.y, n = threadIdx.x;
    float v;
    if      (w == 0) v = Wq[k * C_ + n];
    else if (w == 1) v = Wkv[k * 2 * C_ + n];
    else if (w == 2) v = Wkv[k * 2 * C_ + C_ + n];
    else             v = Wp[k * C_ + n];
    __nv_bfloat16 h = __float2bfloat16_rn(v);
    __nv_bfloat16 l = __float2bfloat16_rn(v - __bfloat162float(h));
    g_whi[(w * C_ + n) * C_ + k] = h;
    g_wlo[(w * C_ + n) * C_ + k] = l;

    if (w == 0) {
        g_kvmat[k * 512 + n]       = 0.f;
        g_kvmat[k * 512 + 256 + n] = 0.f;
        if (n < 16) g_kmean[k * 16 + n] = 0.f;
        if (k == 0) {
            float sp = scale_param[n];
            float s  = (sp > 20.f) ? sp : log1pf(expf(sp));
            g_rscale[n] = 1.f / s;
        }
    }
}

// ---------------- HMMA split-precision GEMM, 64x128 tile, 2 CTA/SM ------------
#define STAGE_SZ 49152
#define PL_AHI 0
#define PL_ALO 8192
#define PL_BHI 16384
#define PL_BLO 32768
#define SM_GTOT (2 * STAGE_SZ)

__global__ void __launch_bounds__(256, 2)
gemm_hmma(const __nv_bfloat16* __restrict__ Ahi, const __nv_bfloat16* __restrict__ Alo,
          const __nv_bfloat16* __restrict__ Bhi, const __nv_bfloat16* __restrict__ Blo,
          const float* __restrict__ bias,
          float* __restrict__ C0, float* __restrict__ C1, float* __restrict__ C2)
{
    extern __shared__ char smem[];
    const uint32_t sb = smem_u32(smem);
    const int tid  = threadIdx.x;
    const int lane = tid & 31, wid = tid >> 5;
    const int wm   = wid & 1,  wn  = wid >> 1;
    const int m0   = blockIdx.y * 64;
    const int n0   = blockIdx.x * 128;
    const int w    = blockIdx.x >> 1;
    const int col0 = (blockIdx.x & 1) * 128;
    float* C = (w == 0) ? C0 : ((w == 1) ? C1 : C2);

    const uint32_t xm   = (uint32_t)(lane & 7) << 4;
    const uint32_t aRow = wm * 32 + (lane & 15);
    const uint32_t aK   = (uint32_t)(lane >> 4) * 16;
    const uint32_t bRow = wn * 32 + (uint32_t)(lane >> 4) * 8 + (lane & 7);
    const uint32_t bK   = (uint32_t)((lane >> 3) & 1) * 16;

    float acc[2][4][4];
    #pragma unroll
    for (int mt = 0; mt < 2; mt++)
        #pragma unroll
        for (int nt = 0; nt < 4; nt++)
            #pragma unroll
            for (int i = 0; i < 4; i++) acc[mt][nt][i] = 0.f;

    auto stage = [&](int c, uint32_t base) {
        #pragma unroll
        for (int j = 0; j < 2; j++) {
            int idx = tid + j * 256;
            int row = idx >> 3, kc = idx & 7;
            uint32_t off = (uint32_t)row * 128 +
                           (uint32_t)((kc * 16) ^ ((row & 7) << 4));
            const size_t goff = (size_t)(m0 + row) * C_ + c * 64 + kc * 8;
            CPA(base + PL_AHI + off, Ahi + goff);
            CPA(base + PL_ALO + off, Alo + goff);
        }
        #pragma unroll
        for (int j = 0; j < 4; j++) {
            int idx = tid + j * 256;
            int row = idx >> 3, kc = idx & 7;
            uint32_t off = (uint32_t)row * 128 +
                           (uint32_t)((kc * 16) ^ ((row & 7) << 4));
            const size_t goff = (size_t)(n0 + row) * C_ + c * 64 + kc * 8;
            CPA(base + PL_BHI + off, Bhi + goff);
            CPA(base + PL_BLO + off, Blo + goff);
        }
    };

    stage(0, sb);
    CPCOMMIT();

    for (int c = 0; c < 4; c++) {
        if (c + 1 < 4) {
            stage(c + 1, sb + (uint32_t)((c + 1) & 1) * STAGE_SZ);
            CPCOMMIT();
            CPWAIT(1);
        } else {
            CPWAIT(0);
        }
        __syncthreads();

        const uint32_t base = sb + (uint32_t)(c & 1) * STAGE_SZ;
        #pragma unroll
        for (int kt = 0; kt < 4; kt++) {
            const uint32_t kx  = ((aK + (uint32_t)kt * 32) ^ xm);
            const uint32_t kbx = ((bK + (uint32_t)kt * 32) ^ xm);
            uint32_t a[2][4], bh[4][2], bl[4][2];
            #pragma unroll
            for (int mt = 0; mt < 2; mt++)
                LDSM4(a[mt], base + PL_AHI + (aRow + mt * 16) * 128 + kx);
            #pragma unroll
            for (int p = 0; p < 2; p++) {
                uint32_t off = (bRow + p * 16) * 128 + kbx;
                uint32_t t[4];
                LDSM4(t, base + PL_BHI + off);
                bh[2*p][0] = t[0]; bh[2*p][1] = t[1];
                bh[2*p+1][0] = t[2]; bh[2*p+1][1] = t[3];
                LDSM4(t, base + PL_BLO + off);
                bl[2*p][0] = t[0]; bl[2*p][1] = t[1];
                bl[2*p+1][0] = t[2]; bl[2*p+1][1] = t[3];
            }
            #pragma unroll
            for (int mt = 0; mt < 2; mt++)
                #pragma unroll
                for (int nt = 0; nt < 4; nt++) {
                    MMA(acc[mt][nt], a[mt], bh[nt]);
                    MMA(acc[mt][nt], a[mt], bl[nt]);
                }
            #pragma unroll
            for (int mt = 0; mt < 2; mt++)
                LDSM4(a[mt], base + PL_ALO + (aRow + mt * 16) * 128 + kx);
            #pragma unroll
            for (int mt = 0; mt < 2; mt++)
                #pragma unroll
                for (int nt = 0; nt < 4; nt++)
                    MMA(acc[mt][nt], a[mt], bh[nt]);
        }
        __syncthreads();
    }

    const int rowb = m0 + wm * 32 + (lane >> 2);
    const int colb = col0 + wn * 32 + (lane & 3) * 2;
    #pragma unroll
    for (int nt = 0; nt < 4; nt++) {
        const int col = colb + nt * 8;
        float2 bv = make_float2(0.f, 0.f);
        if (bias) bv = *(const float2*)(bias + col);
        #pragma unroll
        for (int mt = 0; mt < 2; mt++) {
            float2 v0 = make_float2(acc[mt][nt][0] + bv.x, acc[mt][nt][1] + bv.y);
            float2 v1 = make_float2(acc[mt][nt][2] + bv.x, acc[mt][nt][3] + bv.y);
            *(float2*)(C + (size_t)(rowb + mt * 16) * C_ + col)     = v0;
            *(float2*)(C + (size_t)(rowb + mt * 16 + 8) * C_ + col) = v1;
        }
    }
}

// ---------------- K-only focus nonlinearity + fused kmean ----------------------
__global__ void focus_kernel(const float* __restrict__ pos_enc)
{
    __shared__ float kpart[256];
    const int lane = threadIdx.x & 31;
    const int warp = threadIdx.x >> 5;
    const int row  = blockIdx.x * 8 + warp;
    const int n    = row & (N_ - 1);
    const int b    = row >> 12;
    float* krow = g_K + row * C_;
    const float* prow = pos_enc + n * C_;

    kpart[threadIdx.x] = 0.f;
    __syncthreads();

    float tk3[8];
    float sk2 = 0.f, sk6 = 0.f;
    #pragma unroll
    for (int j = 0; j < 8; j++) {
        int c = lane + j * 32;
        float rs = g_rscale[c];
        float k = fmaxf(krow[c] + prow[c], 0.f);
        k = (k + 1e-6f) * rs;
        float k3 = k * k * k;
        sk2 += k * k; sk6 += k3 * k3; tk3[j] = k3;
    }
    #pragma unroll
    for (int off = 16; off > 0; off >>= 1) {
        sk2 += __shfl_xor_sync(0xffffffffu, sk2, off);
        sk6 += __shfl_xor_sync(0xffffffffu, sk6, off);
    }
    float kf = sqrtf(sk2 / sk6);
    #pragma unroll
    for (int j = 0; j < 8; j++) {
        int c = lane + j * 32;
        float kv = tk3[j] * kf;
        krow[c] = kv;
        atomicAdd(&kpart[c], kv);
    }
    __syncthreads();
    if (warp == 0) {
        #pragma unroll
        for (int j = 0; j < 8; j++) {
            int c = lane + j * 32;
            atomicAdd(&g_kmean[b * C_ + c], kpart[c] * (1.f / (float)N_));
        }
    }
}

// kvmat: float4 loads, double-buffered 32-row tiles, 1 barrier per chunk
__global__ void kvmat_kernel()
{
    const int bh = blockIdx.y;
    const int b  = bh >> 3, h = bh & 7;
    const int ns = blockIdx.x;
    const int t  = threadIdx.x;
    const int d  = t & 31, eg = t >> 5;
    const int r4 = t >> 3, c4 = (t & 7) * 4;
    __shared__ float ks[2][32][32], vs[2][32][32];
    float a0 = 0.f, a1 = 0.f, a2 = 0.f, a3 = 0.f;
    const int base = (b * N_ + ns * 512) * C_ + h * HD;

    {
        const int off = base + r4 * C_ + c4;
        *(float4*)&ks[0][r4][c4] = *(const float4*)&g_K[off];
        *(float4*)&vs[0][r4][c4] = *(const float4*)&g_V[off];
    }
    __syncthreads();
    for (int cc = 0; cc < 16; cc++) {
        const int buf = cc & 1;
        if (cc + 1 < 16) {
            const int off = base + (cc + 1) * 32 * C_ + r4 * C_ + c4;
            *(float4*)&ks[buf ^ 1][r4][c4] = *(const float4*)&g_K[off];
            *(float4*)&vs[buf ^ 1][r4][c4] = *(const float4*)&g_V[off];
        }
        #pragma unroll
        for (int nn = 0; nn < 32; nn++) {
            float  kd = ks[buf][nn][d];
            float4 v4 = *(const float4*)&vs[buf][nn][eg * 4];
            a0 += kd * v4.x; a1 += kd * v4.y; a2 += kd * v4.z; a3 += kd * v4.w;
        }
        __syncthreads();
    }
    const float sc = 1.f / (float)N_;
    const int  o  = (bh * HD + d) * HD + eg * 4;
    atomicAdd(&g_kvmat[o + 0], a0 * sc);
    atomicAdd(&g_kvmat[o + 1], a1 * sc);
    atomicAdd(&g_kvmat[o + 2], a2 * sc);
    atomicAdd(&g_kvmat[o + 3], a3 * sc);
}

// attn with fused Q-focus (R15 version, verified)
__global__ __launch_bounds__(256, 1)
void attn_kernel()
{
    extern __shared__ float sm[];
    float* q_s    = sm;
    float* kvs    = q_s + 256 * 33;
    float* km     = kvs + NH * HD * HD;
    float* o_s    = km + 256;
    float* rowsum = o_s + 32 * 257;

    const int b    = blockIdx.y;
    const int tile = blockIdx.x;
    const int row0 = b * N_ + tile * 32;
    const int t    = threadIdx.x;

    if (t < 64) rowsum[t] = 0.f;

    const float rs = g_rscale[t];
    #pragma unroll
    for (int j = 0; j < 32; j++) {
        float v = fmaxf(g_Q[(row0 + j) * C_ + t], 0.f);
        q_s[t * 33 + j] = (v + 1e-6f) * rs;
    }
    for (int j = t; j < NH * HD * HD; j += 256)
        kvs[j] = g_kvmat[b * NH * HD * HD + j];
    km[t] = g_kmean[b * C_ + t];
    __syncthreads();

    const int n = t & 31, h = t >> 5;
    float qv[32];
    float s_z = 0.f, s2 = 0.f, s6 = 0.f;
    #pragma unroll
    for (int d = 0; d < 32; d++) {
        float v  = q_s[(h * HD + d) * 33 + n];
        float v3 = v * v * v;
        qv[d] = v3;
        s2 += v * v;
        s6 += v3 * v3;
        s_z += v3 * km[h * HD + d];
    }
    atomicAdd(&rowsum[n * 2],     s2);
    atomicAdd(&rowsum[n * 2 + 1], s6);

    float acc[32];
    #pragma unroll
    for (int e = 0; e < 32; e++) acc[e] = 0.f;
    const float* kvh = kvs + h * HD * HD;
    #pragma unroll 4
    for (int d = 0; d < 32; d++) {
        float qd = qv[d];
        #pragma unroll
        for (int e4 = 0; e4 < 8; e4++) {
            float4 kv = *(const float4*)&kvh[d * HD + e4 * 4];
            acc[e4*4+0] += qd * kv.x;
            acc[e4*4+1] += qd * kv.y;
            acc[e4*4+2] += qd * kv.z;
            acc[e4*4+3] += qd * kv.w;
        }
    }
    __syncthreads();
    const float qf  = sqrtf(rowsum[n * 2] / rowsum[n * 2 + 1]);
    const float fac = qf / (qf * s_z + 1e-6f);
    #pragma unroll
    for (int e = 0; e < 32; e++)
        o_s[n * 257 + h * HD + e] = acc[e] * fac;
    __syncthreads();
    #pragma unroll
    for (int j = 0; j < 32; j++)
        g_O[(row0 + j) * C_ + t] = o_s[j * 257 + t];
}

// dwconv — R13/R15 version
__global__ void dwconv_kernel(const float* __restrict__ Wc,
                              const float* __restrict__ bc)
{
    const int c  = threadIdx.x;
    const int y  = blockIdx.x;
    const int b  = blockIdx.y;
    const int ch = c & (HD - 1);
    float w[25];
    #pragma unroll
    for (int i = 0; i < 25; i++) w[i] = Wc[ch * 25 + i];
    const float bias = bc[ch];

    const float* vb = g_V + (b * N_) * C_ + c;
    const float* ob = g_O + (b * N_) * C_ + c;
    __nv_bfloat16* ph = g_ohi + (size_t)(b * N_) * C_ + c;
    __nv_bfloat16* pl = g_olo + (size_t)(b * N_) * C_ + c;

    float win[5][5];
    #pragma unroll
    for (int wy = 0; wy < 5; wy++) {
        int Y = y + wy - 2;
        bool yin = (Y >= 0) && (Y < 64);
        #pragma unroll
        for (int wx = 0; wx < 5; wx++) {
            int X = wx - 2;
            win[wy][wx] = (yin && X >= 0) ? vb[(Y * 64 + X) * C_] : 0.f;
        }
    }
    for (int x = 0; x < 64; x++) {
        float acc = bias;
        #pragma unroll
        for (int wy = 0; wy < 5; wy++)
            #pragma unroll
            for (int wx = 0; wx < 5; wx++)
                acc += win[wy][wx] * w[wy * 5 + wx];
        float val = ob[(y * 64 + x) * C_] + acc;
        __nv_bfloat16 h = __float2bfloat16_rn(val);
        __nv_bfloat16 l = __float2bfloat16_rn(val - __bfloat162float(h));
        ph[(y * 64 + x) * C_] = h;
        pl[(y * 64 + x) * C_] = l;
        #pragma unroll
        for (int wy = 0; wy < 5; wy++)
            #pragma unroll
            for (int wx = 0; wx < 4; wx++) win[wy][wx] = win[wy][wx + 1];
        int X = x + 3;
        bool xin = X < 64;
        #pragma unroll
        for (int wy = 0; wy < 5; wy++) {
            int Y = y + wy - 2;
            win[wy][4] = (xin && Y >= 0 && Y < 64) ? vb[(Y * 64 + X) * C_] : 0.f;
        }
    }
}

// ------------------------------- host launcher -------------------------------
extern "C" void kernel_launch(void* const* d_in, const int* in_sizes, int n_in,
                              void* d_out, int out_size)
{
    const float* x     = (const float*)d_in[0];
    const float* Wq    = (const float*)d_in[1];
    const float* Wkv   = (const float*)d_in[2];
    const float* Wp    = (const float*)d_in[3];
    const float* bp    = (const float*)d_in[4];
    const float* scale = (const float*)d_in[5];
    const float* pos   = (const float*)d_in[6];
    const float* dwcw  = (const float*)d_in[7];
    const float* dwcb  = (const float*)d_in[8];
    float* out = (float*)d_out;

    float *Qp, *Kp, *Vp, *Op;
    __nv_bfloat16 *xhi, *xlo, *ohi, *olo, *whi, *wlo;
    cudaGetSymbolAddress((void**)&Qp,  g_Q);
    cudaGetSymbolAddress((void**)&Kp,  g_K);
    cudaGetSymbolAddress((void**)&Vp,  g_V);
    cudaGetSymbolAddress((void**)&Op,  g_O);
    cudaGetSymbolAddress((void**)&xhi, g_xhi);
    cudaGetSymbolAddress((void**)&xlo, g_xlo);
    cudaGetSymbolAddress((void**)&ohi, g_ohi);
    cudaGetSymbolAddress((void**)&olo, g_olo);
    cudaGetSymbolAddress((void**)&whi, g_whi);
    cudaGetSymbolAddress((void**)&wlo, g_wlo);

    const int ATTN_SMEM = (256 * 33 + NH * HD * HD + 256 + 32 * 257 + 64) * 4;
    static bool attr_done = false;
    if (!attr_done) {
        cudaFuncSetAttribute(attn_kernel,
                             cudaFuncAttributeMaxDynamicSharedMemorySize, ATTN_SMEM);
        cudaFuncSetAttribute(gemm_hmma,
                             cudaFuncAttributeMaxDynamicSharedMemorySize, SM_GTOT);
        attr_done = true;
    }

    const int WS = C_ * C_;

    cvt_hilo_kernel<<<(M_ * C_ / 4 + 255) / 256, 256>>>(x, xhi, xlo, M_ * C_ / 4); // 0
    prep_w_kernel<<<dim3(C_, 4), 256>>>(Wq, Wkv, Wp, scale);                       // 1

    gemm_hmma<<<dim3(6, M_ / 64), 256, SM_GTOT>>>(xhi, xlo, whi, wlo,              // 2
                                                  nullptr, Qp, Kp, Vp);

    focus_kernel<<<M_ / 8, 256>>>(pos);                                            // 3 (profiled)

    kvmat_kernel<<<dim3(8, B_ * NH), 256>>>();                                     // 4

    attn_kernel<<<dim3(N_ / 32, B_), 256, ATTN_SMEM>>>();                          // 5

    dwconv_kernel<<<dim3(64, B_), 256>>>(dwcw, dwcb);                              // 6

    gemm_hmma<<<dim3(2, M_ / 64), 256, SM_GTOT>>>(ohi, olo,                        // 7
                                                  whi + 3 * WS, wlo + 3 * WS,
                                                  bp, out, out, out);
}